// round 7
// baseline (speedup 1.0000x reference)
#include <cuda_runtime.h>

// filtfilt, 2nd-order Butterworth, odd ext padlen=9, zero init state.
// Linearity => max|x| normalization cancels; omitted.
// Warm-up truncation: |pole|=0.577, 0.577^20 = 1.7e-5 << 1e-3 tolerance.
// R6: in-place single smem buffer, register warm-ups, static smem addressing.

#define T_THREADS 128
#define CHUNK_C   32
#define S_OUT     (T_THREADS * CHUNK_C)   // 4096
#define W_WARM    20
#define PADLEN    9
#define N_SAMP    32768
#define E_LEN     (N_SAMP + 2 * PADLEN)   // 32786
#define N_CHUNKS  (N_SAMP / S_OUT)        // 8

#define E_MAX   (S_OUT + 2 * W_WARM)              // 4136
#define E_PAD   (E_MAX + (E_MAX >> 5) + 2)        // padded physical size

// physical offset within a thread's 33-stride base for local offset m (m >= 0)
__device__ __forceinline__ int poff(int m) { return m + (m >> 5); }

__global__ void __launch_bounds__(T_THREADS)
filtfilt_kernel(const float* __restrict__ x, float* __restrict__ out)
{
    __shared__ float buf[E_PAD];

    const int row   = blockIdx.y;
    const int chunk = blockIdx.x;
    const int tid   = threadIdx.x;

    const float* xr   = x   + (long)row * N_SAMP;
    float*       outr = out + (long)row * N_SAMP;

    const int t0 = PADLEN + chunk * S_OUT;   // first kept output, e-space

    // coefficients (a0=1); state-space: z1'=c1*x+d1*z1+z2 ; z2'=c2*x+d2*z1 ; y=b0*x+z1
    const float b0 = 0.0976310729378175f;
    const float b1 = 0.195262145875635f;
    const float b2 = 0.0976310729378175f;
    const float a1 = -0.9428090415820634f;
    const float a2 = 0.33333333333333337f;
    const float c1 = b1 - a1 * b0;
    const float c2 = b2 - a2 * b0;
    const float d1 = -a1;
    const float d2 = -a2;

    // ---- stage: buffer index i <-> e-space t = t0 - W + i; zero-fill outside ----
    for (int i = tid; i < E_MAX; i += T_THREADS) {
        int t = t0 - W_WARM + i;
        float v = 0.0f;
        if (t >= PADLEN) {
            if (t < PADLEN + N_SAMP)
                v = xr[t - PADLEN];
            else if (t < E_LEN)
                v = 2.0f * xr[N_SAMP - 1] - xr[2 * N_SAMP + PADLEN - 2 - t];
            // t >= E_LEN: stays 0 (exact zero-state tail for backward pass)
        } else if (t >= 0) {
            v = 2.0f * xr[0] - xr[PADLEN - t];
        }
        // t < 0: stays 0 (exact: zero input + zero state)
        buf[i + (i >> 5)] = v;
    }
    __syncthreads();

    float* base = buf + tid * 33;       // thread-local padded base
    const int u = t0 + tid * CHUNK_C;   // first kept sample of this thread

    float pre[W_WARM];
    float z1, z2;

    // ================= forward pass =================
    // preload warm-up inputs (neighbor's kept region) into registers
    #pragma unroll
    for (int j = 0; j < W_WARM; ++j) pre[j] = base[j];       // poff(j)=j, j<32

    z1 = 0.0f; z2 = 0.0f;
    #pragma unroll
    for (int j = 0; j < W_WARM; ++j) {                        // reg-only warm-up
        float ev = pre[j];
        float nz1 = fmaf(d1, z1, fmaf(c1, ev, z2));
        z2 = fmaf(d2, z1, c2 * ev);
        z1 = nz1;
    }
    __syncthreads();   // all preloads done -> safe to overwrite e with y1

    #pragma unroll
    for (int j = 0; j < CHUNK_C; ++j) {                       // kept, in place
        const int p = poff(W_WARM + j);                       // compile-time
        float ev = base[p];
        base[p] = fmaf(b0, ev, z1);
        float nz1 = fmaf(d1, z1, fmaf(c1, ev, z2));
        z2 = fmaf(d2, z1, c2 * ev);
        z1 = nz1;
    }
    if (tid == T_THREADS - 1) {                               // +W extension for bwd warm-up
        #pragma unroll
        for (int j = 0; j < W_WARM; ++j) {
            int t = u + CHUNK_C + j;
            if (t < E_LEN) {                                  // keep zeros beyond end
                const int p = poff(W_WARM + CHUNK_C + j);
                float ev = base[p];
                base[p] = fmaf(b0, ev, z1);
                float nz1 = fmaf(d1, z1, fmaf(c1, ev, z2));
                z2 = fmaf(d2, z1, c2 * ev);
                z1 = nz1;
            }
        }
    }
    __syncthreads();

    // ================= backward pass =================
    #pragma unroll
    for (int j = 0; j < W_WARM; ++j)                          // preload y1 warm-up
        pre[j] = base[poff(CHUNK_C + W_WARM + j)];

    z1 = 0.0f; z2 = 0.0f;
    #pragma unroll
    for (int j = W_WARM - 1; j >= 0; --j) {                   // reg-only warm-up
        float v = pre[j];
        float nz1 = fmaf(d1, z1, fmaf(c1, v, z2));
        z2 = fmaf(d2, z1, c2 * v);
        z1 = nz1;
    }
    __syncthreads();   // all preloads done -> safe to overwrite y1 with y2

    #pragma unroll
    for (int j = CHUNK_C - 1; j >= 0; --j) {                  // kept, in place
        const int p = poff(W_WARM + j);
        float v = base[p];
        base[p] = fmaf(b0, v, z1);
        float nz1 = fmaf(d1, z1, fmaf(c1, v, z2));
        z2 = fmaf(d2, z1, c2 * v);
        z1 = nz1;
    }
    __syncthreads();

    // ---- coalesced float4 writeout ----
    float4* o4 = (float4*)(outr + (t0 - PADLEN));
    #pragma unroll
    for (int k = 0; k < S_OUT / 4 / T_THREADS; ++k) {         // 8 iters
        int e = tid + k * T_THREADS;
        int i = 4 * e + W_WARM;
        float4 v;
        v.x = buf[(i + 0) + ((i + 0) >> 5)];
        v.y = buf[(i + 1) + ((i + 1) >> 5)];
        v.z = buf[(i + 2) + ((i + 2) >> 5)];
        v.w = buf[(i + 3) + ((i + 3) >> 5)];
        o4[e] = v;
    }
}

extern "C" void kernel_launch(void* const* d_in, const int* in_sizes, int n_in,
                              void* d_out, int out_size)
{
    const float* x = (const float*)d_in[0];
    float* out = (float*)d_out;

    const int rows = in_sizes[0] / N_SAMP;  // 1024
    dim3 grid(N_CHUNKS, rows);
    filtfilt_kernel<<<grid, T_THREADS>>>(x, out);
}

// round 11
// speedup vs baseline: 1.4168x; 1.4168x over previous
#include <cuda_runtime.h>

// filtfilt, 2nd-order Butterworth, odd ext padlen=9, zero init state.
// Linearity => max|x| normalization cancels; omitted.
// Warm-up truncation: |pole|=0.577, 0.577^20 = 1.7e-5 << 1e-3 tolerance.
// R8/R9: block-4 matrix-power recurrence (2cyc/sample critical path),
//     bulk register staging of kept inputs, conflict-free lane-uniform smem.
//     (R9 = identical resubmit after infra failure.)

#define T_THREADS 128
#define CHUNK_C   32
#define S_OUT     (T_THREADS * CHUNK_C)   // 4096
#define W_WARM    20
#define PADLEN    9
#define N_SAMP    32768
#define E_LEN     (N_SAMP + 2 * PADLEN)   // 32786
#define N_CHUNKS  (N_SAMP / S_OUT)        // 8
#define E_MAX     (S_OUT + 2 * W_WARM)    // 4136
#define E_PHYS    (E_MAX + (E_MAX >> 5) + 2)

// ---- compile-time constant derivation in double ----
#define B0d 0.0976310729378175
#define B1d 0.195262145875635
#define B2d 0.0976310729378175
#define A1d (-0.9428090415820634)
#define A2d (0.33333333333333337)
#define D1d (-(A1d))
#define D2d (-(A2d))
#define C1d (B1d - (A1d) * B0d)
#define C2d (B2d - (A2d) * B0d)
// M = [[D1,1],[D2,0]] ; powers
#define M2_11d (D1d*D1d + D2d)
#define M2_12d (D1d)
#define M2_21d (D2d*D1d)
#define M2_22d (D2d)
#define M3_11d (M2_11d*D1d + M2_12d*D2d)
#define M3_12d (M2_11d)
#define M3_21d (M2_21d*D1d + M2_22d*D2d)
#define M3_22d (M2_21d)
#define M4_11d (M3_11d*D1d + M3_12d*D2d)
#define M4_12d (M3_11d)
#define M4_21d (M3_21d*D1d + M3_22d*D2d)
#define M4_22d (M3_21d)
// input weight vectors: w3 = g = [C1,C2], w2 = M g, w1 = M2 g, w0 = M3 g
#define W2_1d (D1d*C1d + C2d)
#define W2_2d (D2d*C1d)
#define W1_1d (M2_11d*C1d + M2_12d*C2d)
#define W1_2d (M2_21d*C1d + M2_22d*C2d)
#define W0_1d (M3_11d*C1d + M3_12d*C2d)
#define W0_2d (M3_21d*C1d + M3_22d*C2d)

#define fB0    ((float)(B0d))
#define fD1    ((float)(D1d))
#define fD2    ((float)(D2d))
#define fC1    ((float)(C1d))
#define fC2    ((float)(C2d))
#define fM2_11 ((float)(M2_11d))
#define fM2_12 ((float)(M2_12d))
#define fM3_11 ((float)(M3_11d))
#define fM3_12 ((float)(M3_12d))
#define fM4_11 ((float)(M4_11d))
#define fM4_12 ((float)(M4_12d))
#define fM4_21 ((float)(M4_21d))
#define fM4_22 ((float)(M4_22d))
#define fW2_1  ((float)(W2_1d))
#define fW2_2  ((float)(W2_2d))
#define fW1_1  ((float)(W1_1d))
#define fW1_2  ((float)(W1_2d))
#define fW0_1  ((float)(W0_1d))
#define fW0_2  ((float)(W0_2d))

__device__ __forceinline__ int poff(int m) { return m + (m >> 5); }

// advance state over 4 samples, no outputs (warm-up)
__device__ __forceinline__ void warm4(const float* v, float& z1, float& z2)
{
    float E1 = fmaf(fW0_1, v[0], fmaf(fW1_1, v[1], fmaf(fW2_1, v[2], fC1 * v[3])));
    float E2 = fmaf(fW0_2, v[0], fmaf(fW1_2, v[1], fmaf(fW2_2, v[2], fC2 * v[3])));
    float nz1 = fmaf(fM4_11, z1, fmaf(fM4_12, z2, E1));
    z2        = fmaf(fM4_21, z1, fmaf(fM4_22, z2, E2));
    z1 = nz1;
}

// advance over 4 samples, producing outputs in place (v[k] <- y[k])
__device__ __forceinline__ void kept4(float* v, float& z1, float& z2)
{
    float e0 = v[0], e1 = v[1], e2 = v[2], e3 = v[3];
    float E1 = fmaf(fW0_1, e0, fmaf(fW1_1, e1, fmaf(fW2_1, e2, fC1 * e3)));
    float E2 = fmaf(fW0_2, e0, fmaf(fW1_2, e1, fmaf(fW2_2, e2, fC2 * e3)));
    // intermediate z1 states, all derived from block-start state (ILP, off-chain)
    float z1a = fmaf(fD1,    z1, fmaf(fC1,    e0, z2));
    float z1b = fmaf(fM2_11, z1, fmaf(fM2_12, z2, fmaf(fW2_1, e0, fC1 * e1)));
    float z1c = fmaf(fM3_11, z1, fmaf(fM3_12, z2, fmaf(fW1_1, e0, fmaf(fW2_1, e1, fC1 * e2))));
    v[0] = fmaf(fB0, e0, z1);
    v[1] = fmaf(fB0, e1, z1a);
    v[2] = fmaf(fB0, e2, z1b);
    v[3] = fmaf(fB0, e3, z1c);
    float nz1 = fmaf(fM4_11, z1, fmaf(fM4_12, z2, E1));
    z2        = fmaf(fM4_21, z1, fmaf(fM4_22, z2, E2));
    z1 = nz1;
}

__global__ void __launch_bounds__(T_THREADS, 8)
filtfilt_kernel(const float* __restrict__ x, float* __restrict__ out)
{
    __shared__ float buf[E_PHYS];

    const int row   = blockIdx.y;
    const int chunk = blockIdx.x;
    const int tid   = threadIdx.x;

    const float* xr   = x   + (long)row * N_SAMP;
    float*       outr = out + (long)row * N_SAMP;

    const int t0 = PADLEN + chunk * S_OUT;

    // ---- stage extended signal; interior chunks are branch-free ----
    if (chunk != 0 && chunk != N_CHUNKS - 1) {
        const float* src = xr + (t0 - W_WARM - PADLEN);
        #pragma unroll
        for (int k = 0; k < (E_MAX + T_THREADS - 1) / T_THREADS; ++k) {
            int i = tid + k * T_THREADS;
            if (i < E_MAX) buf[i + (i >> 5)] = src[i];
        }
    } else {
        for (int i = tid; i < E_MAX; i += T_THREADS) {
            int t = t0 - W_WARM + i;
            float v = 0.0f;
            if (t >= PADLEN) {
                if (t < PADLEN + N_SAMP)
                    v = xr[t - PADLEN];
                else if (t < E_LEN)
                    v = 2.0f * xr[N_SAMP - 1] - xr[2 * N_SAMP + PADLEN - 2 - t];
                // t >= E_LEN stays 0 (exact zero-state tail for backward pass)
            } else if (t >= 0) {
                v = 2.0f * xr[0] - xr[PADLEN - t];
            }
            // t < 0 stays 0 (exact: zero input + zero state)
            buf[i + (i >> 5)] = v;
        }
    }
    __syncthreads();

    float* base = buf + tid * 33;
    float z1, z2;

    // ================= forward pass =================
    {
        float pre[W_WARM];
        #pragma unroll
        for (int j = 0; j < W_WARM; ++j) pre[j] = base[j];   // poff(j)=j for j<32
        z1 = 0.0f; z2 = 0.0f;
        #pragma unroll
        for (int b = 0; b < W_WARM / 4; ++b) warm4(pre + 4 * b, z1, z2);

        float ev[CHUNK_C];
        #pragma unroll
        for (int j = 0; j < CHUNK_C; ++j) ev[j] = base[poff(W_WARM + j)];
        __syncthreads();   // all cross-thread reads done -> safe to overwrite

        #pragma unroll
        for (int b = 0; b < CHUNK_C / 4; ++b) kept4(ev + 4 * b, z1, z2);
        #pragma unroll
        for (int j = 0; j < CHUNK_C; ++j) base[poff(W_WARM + j)] = ev[j];

        if (tid == T_THREADS - 1) {   // +W extension for backward warm-up
            const int u = t0 + tid * CHUNK_C;
            #pragma unroll
            for (int j = 0; j < W_WARM; ++j) {
                if (u + CHUNK_C + j < E_LEN) {
                    int p = poff(W_WARM + CHUNK_C + j);
                    float e = base[p];
                    base[p] = fmaf(fB0, e, z1);
                    float nz1 = fmaf(fD1, z1, fmaf(fC1, e, z2));
                    z2 = fmaf(fD2, z1, fC2 * e);
                    z1 = nz1;
                }
            }
        }
    }
    __syncthreads();

    // ================= backward pass =================
    {
        float pre[W_WARM];   // y1 above this chunk, reversed processing order
        #pragma unroll
        for (int r = 0; r < W_WARM; ++r)
            pre[r] = base[poff(CHUNK_C + 2 * W_WARM - 1 - r)];
        z1 = 0.0f; z2 = 0.0f;
        #pragma unroll
        for (int b = 0; b < W_WARM / 4; ++b) warm4(pre + 4 * b, z1, z2);

        float ev[CHUNK_C];   // own kept y1, reversed
        #pragma unroll
        for (int k = 0; k < CHUNK_C; ++k)
            ev[k] = base[poff(W_WARM + CHUNK_C - 1 - k)];
        __syncthreads();   // all cross-thread reads done -> safe to overwrite

        #pragma unroll
        for (int b = 0; b < CHUNK_C / 4; ++b) kept4(ev + 4 * b, z1, z2);
        #pragma unroll
        for (int k = 0; k < CHUNK_C; ++k)
            base[poff(W_WARM + CHUNK_C - 1 - k)] = ev[k];
    }
    __syncthreads();

    // ---- coalesced float4 writeout ----
    float4* o4 = (float4*)(outr + (t0 - PADLEN));
    #pragma unroll
    for (int k = 0; k < S_OUT / 4 / T_THREADS; ++k) {   // 8 iters
        int e = tid + k * T_THREADS;
        int i = 4 * e + W_WARM;
        float4 v;
        v.x = buf[(i + 0) + ((i + 0) >> 5)];
        v.y = buf[(i + 1) + ((i + 1) >> 5)];
        v.z = buf[(i + 2) + ((i + 2) >> 5)];
        v.w = buf[(i + 3) + ((i + 3) >> 5)];
        o4[e] = v;
    }
}

extern "C" void kernel_launch(void* const* d_in, const int* in_sizes, int n_in,
                              void* d_out, int out_size)
{
    const float* x = (const float*)d_in[0];
    float* out = (float*)d_out;

    const int rows = in_sizes[0] / N_SAMP;  // 1024
    dim3 grid(N_CHUNKS, rows);
    filtfilt_kernel<<<grid, T_THREADS>>>(x, out);
}

// round 13
// speedup vs baseline: 1.5363x; 1.0843x over previous
#include <cuda_runtime.h>

// filtfilt, 2nd-order Butterworth, odd ext padlen=9, zero init state.
// Linearity => max|x| normalization cancels; omitted.
// Warm-up truncation: |pole|=3^-0.5, 3^-8 = 1.5e-4 << 1e-3 tolerance.
// R12: y1 kept in registers (smem exchange only for W boundary values),
//      float4 LDS/STS everywhere (stride-36 padding), streamed warm-ups.

#define T_THREADS 128
#define CHUNK_C   32
#define S_OUT     (T_THREADS * CHUNK_C)   // 4096
#define W_WARM    16
#define PADLEN    9
#define N_SAMP    32768
#define E_LEN     (N_SAMP + 2 * PADLEN)   // 32786
#define N_CHUNKS  (N_SAMP / S_OUT)        // 8
#define E_MAX     (S_OUT + 2 * W_WARM)    // 4128
#define E_PHYS    4648                    // PH(4127)=4639, + slack
#define XSTRIDE   17
#define X_SIZE    (T_THREADS * XSTRIDE)   // 2176

// ---- compile-time constants (derived in double, folded) ----
#define B0d 0.0976310729378175
#define B1d 0.195262145875635
#define B2d 0.0976310729378175
#define A1d (-0.9428090415820634)
#define A2d (0.33333333333333337)
#define D1d (-(A1d))
#define D2d (-(A2d))
#define C1d (B1d - (A1d) * B0d)
#define C2d (B2d - (A2d) * B0d)
#define M2_11d (D1d*D1d + D2d)
#define M2_12d (D1d)
#define M2_21d (D2d*D1d)
#define M2_22d (D2d)
#define M3_11d (M2_11d*D1d + M2_12d*D2d)
#define M3_12d (M2_11d)
#define M3_21d (M2_21d*D1d + M2_22d*D2d)
#define M3_22d (M2_21d)
#define M4_11d (M3_11d*D1d + M3_12d*D2d)
#define M4_12d (M3_11d)
#define M4_21d (M3_21d*D1d + M3_22d*D2d)
#define M4_22d (M3_21d)
#define W2_1d (D1d*C1d + C2d)
#define W2_2d (D2d*C1d)
#define W1_1d (M2_11d*C1d + M2_12d*C2d)
#define W1_2d (M2_21d*C1d + M2_22d*C2d)
#define W0_1d (M3_11d*C1d + M3_12d*C2d)
#define W0_2d (M3_21d*C1d + M3_22d*C2d)

#define fB0    ((float)(B0d))
#define fD1    ((float)(D1d))
#define fD2    ((float)(D2d))
#define fC1    ((float)(C1d))
#define fC2    ((float)(C2d))
#define fM2_11 ((float)(M2_11d))
#define fM2_12 ((float)(M2_12d))
#define fM3_11 ((float)(M3_11d))
#define fM3_12 ((float)(M3_12d))
#define fM4_11 ((float)(M4_11d))
#define fM4_12 ((float)(M4_12d))
#define fM4_21 ((float)(M4_21d))
#define fM4_22 ((float)(M4_22d))
#define fW2_1  ((float)(W2_1d))
#define fW2_2  ((float)(W2_2d))
#define fW1_1  ((float)(W1_1d))
#define fW1_2  ((float)(W1_2d))
#define fW0_1  ((float)(W0_1d))
#define fW0_2  ((float)(W0_2d))

// physical smem word: groups of 32 words padded to 36 (lane stride 144B,
// conflict-free for 32-bit and 128-bit accesses)
__device__ __forceinline__ int PH(int i) { return i + ((i >> 5) << 2); }

// advance state over 4 samples (no outputs)
__device__ __forceinline__ void warm4(float v0, float v1, float v2, float v3,
                                      float& z1, float& z2)
{
    float E1 = fmaf(fW0_1, v0, fmaf(fW1_1, v1, fmaf(fW2_1, v2, fC1 * v3)));
    float E2 = fmaf(fW0_2, v0, fmaf(fW1_2, v1, fmaf(fW2_2, v2, fC2 * v3)));
    float nz1 = fmaf(fM4_11, z1, fmaf(fM4_12, z2, E1));
    z2        = fmaf(fM4_21, z1, fmaf(fM4_22, z2, E2));
    z1 = nz1;
}

// advance over 4 samples, replacing inputs with outputs (in registers)
__device__ __forceinline__ void kept4(float& v0, float& v1, float& v2, float& v3,
                                      float& z1, float& z2)
{
    float e0 = v0, e1 = v1, e2 = v2, e3 = v3;
    float E1 = fmaf(fW0_1, e0, fmaf(fW1_1, e1, fmaf(fW2_1, e2, fC1 * e3)));
    float E2 = fmaf(fW0_2, e0, fmaf(fW1_2, e1, fmaf(fW2_2, e2, fC2 * e3)));
    float z1a = fmaf(fD1,    z1, fmaf(fC1,    e0, z2));
    float z1b = fmaf(fM2_11, z1, fmaf(fM2_12, z2, fmaf(fW2_1, e0, fC1 * e1)));
    float z1c = fmaf(fM3_11, z1, fmaf(fM3_12, z2, fmaf(fW1_1, e0, fmaf(fW2_1, e1, fC1 * e2))));
    v0 = fmaf(fB0, e0, z1);
    v1 = fmaf(fB0, e1, z1a);
    v2 = fmaf(fB0, e2, z1b);
    v3 = fmaf(fB0, e3, z1c);
    float nz1 = fmaf(fM4_11, z1, fmaf(fM4_12, z2, E1));
    z2        = fmaf(fM4_21, z1, fmaf(fM4_22, z2, E2));
    z1 = nz1;
}

__global__ void __launch_bounds__(T_THREADS, 8)
filtfilt_kernel(const float* __restrict__ x, float* __restrict__ out)
{
    __shared__ __align__(16) float buf[E_PHYS];
    __shared__ float xchg[X_SIZE];

    const int row   = blockIdx.y;
    const int chunk = blockIdx.x;
    const int tid   = threadIdx.x;

    const float* xr   = x   + (long)row * N_SAMP;
    float*       outr = out + (long)row * N_SAMP;

    const int t0 = PADLEN + chunk * S_OUT;

    // ---- stage extended signal; buf[i] <-> t = t0 - W + i ----
    if (chunk != 0 && chunk != N_CHUNKS - 1) {
        const float* src = xr + (chunk * S_OUT - W_WARM);   // t0 - W - PADLEN
        #pragma unroll
        for (int k = 0; k < (E_MAX + T_THREADS - 1) / T_THREADS; ++k) {
            int i = tid + k * T_THREADS;
            if (i < E_MAX) buf[PH(i)] = src[i];
        }
    } else {
        for (int i = tid; i < E_MAX; i += T_THREADS) {
            int t = t0 - W_WARM + i;
            float v = 0.0f;
            if (t >= PADLEN) {
                if (t < PADLEN + N_SAMP)
                    v = xr[t - PADLEN];
                else if (t < E_LEN)
                    v = 2.0f * xr[N_SAMP - 1] - xr[2 * N_SAMP + PADLEN - 2 - t];
                // t >= E_LEN stays 0
            } else if (t >= 0) {
                v = 2.0f * xr[0] - xr[PADLEN - t];
            }
            // t < 0 stays 0 (exact: zero input + zero state)
            buf[PH(i)] = v;
        }
    }
    __syncthreads();

    float* bp = buf + 36 * tid;          // thread-local padded base (16B-aligned)
    const int u = t0 + tid * CHUNK_C;    // first kept sample (e-space)
    float z1, z2;
    float ev[CHUNK_C];                   // inputs -> y1 -> y2, all in registers
    float tmp[W_WARM];                   // tid==127: forward-extension y1

    // ================= forward pass =================
    z1 = 0.0f; z2 = 0.0f;
    // warm-up streamed from smem (offsets 0..15 in own padded group)
    warm4(bp[0],  bp[1],  bp[2],  bp[3],  z1, z2);
    warm4(bp[4],  bp[5],  bp[6],  bp[7],  z1, z2);
    warm4(bp[8],  bp[9],  bp[10], bp[11], z1, z2);
    warm4(bp[12], bp[13], bp[14], bp[15], z1, z2);

    // kept inputs: logical i = 32*tid + 16 + j -> offsets 16..31 then 36..51
    {
        float4 a0 = *reinterpret_cast<const float4*>(bp + 16);
        float4 a1 = *reinterpret_cast<const float4*>(bp + 20);
        float4 a2 = *reinterpret_cast<const float4*>(bp + 24);
        float4 a3 = *reinterpret_cast<const float4*>(bp + 28);
        float4 a4 = *reinterpret_cast<const float4*>(bp + 36);
        float4 a5 = *reinterpret_cast<const float4*>(bp + 40);
        float4 a6 = *reinterpret_cast<const float4*>(bp + 44);
        float4 a7 = *reinterpret_cast<const float4*>(bp + 48);
        ev[0]=a0.x; ev[1]=a0.y; ev[2]=a0.z; ev[3]=a0.w;
        ev[4]=a1.x; ev[5]=a1.y; ev[6]=a1.z; ev[7]=a1.w;
        ev[8]=a2.x; ev[9]=a2.y; ev[10]=a2.z; ev[11]=a2.w;
        ev[12]=a3.x; ev[13]=a3.y; ev[14]=a3.z; ev[15]=a3.w;
        ev[16]=a4.x; ev[17]=a4.y; ev[18]=a4.z; ev[19]=a4.w;
        ev[20]=a5.x; ev[21]=a5.y; ev[22]=a5.z; ev[23]=a5.w;
        ev[24]=a6.x; ev[25]=a6.y; ev[26]=a6.z; ev[27]=a6.w;
        ev[28]=a7.x; ev[29]=a7.y; ev[30]=a7.z; ev[31]=a7.w;
    }
    #pragma unroll
    for (int b = 0; b < CHUNK_C / 4; ++b)
        kept4(ev[4*b], ev[4*b+1], ev[4*b+2], ev[4*b+3], z1, z2);
    // ev now holds y1 for [u, u+32)

    if (tid == T_THREADS - 1) {
        // continue recurrence over the next W inputs (offsets 52..67 = i 4112..4127)
        float zz1 = z1, zz2 = z2;
        #pragma unroll
        for (int j = 0; j < W_WARM; ++j) {
            float e = bp[52 + j];
            float y = fmaf(fB0, e, zz1);
            float nz1 = fmaf(fD1, zz1, fmaf(fC1, e, zz2));
            zz2 = fmaf(fD2, zz1, fC2 * e);
            zz1 = nz1;
            tmp[j] = (u + CHUNK_C + j < E_LEN) ? y : 0.0f;  // exact zero tail
        }
    }

    // exchange: first W y1 values go to the left neighbor's backward warm-up
    #pragma unroll
    for (int j = 0; j < W_WARM; ++j)
        xchg[XSTRIDE * tid + j] = ev[j];
    __syncthreads();

    // ================= backward pass =================
    z1 = 0.0f; z2 = 0.0f;
    if (tid < T_THREADS - 1) {
        const float* xc = xchg + XSTRIDE * (tid + 1);   // y1[u+32+j], j=0..15
        warm4(xc[15], xc[14], xc[13], xc[12], z1, z2);
        warm4(xc[11], xc[10], xc[9],  xc[8],  z1, z2);
        warm4(xc[7],  xc[6],  xc[5],  xc[4],  z1, z2);
        warm4(xc[3],  xc[2],  xc[1],  xc[0],  z1, z2);
    } else {
        warm4(tmp[15], tmp[14], tmp[13], tmp[12], z1, z2);
        warm4(tmp[11], tmp[10], tmp[9],  tmp[8],  z1, z2);
        warm4(tmp[7],  tmp[6],  tmp[5],  tmp[4],  z1, z2);
        warm4(tmp[3],  tmp[2],  tmp[1],  tmp[0],  z1, z2);
    }
    #pragma unroll
    for (int b = 0; b < CHUNK_C / 4; ++b)
        kept4(ev[31-4*b], ev[30-4*b], ev[29-4*b], ev[28-4*b], z1, z2);
    // ev now holds y2 for [u, u+32)

    // stage y2: output position 32*tid+j -> word 36*tid+j (own group, float4)
    {
        float4 s;
        s.x=ev[0];  s.y=ev[1];  s.z=ev[2];  s.w=ev[3];  *reinterpret_cast<float4*>(bp+0)  = s;
        s.x=ev[4];  s.y=ev[5];  s.z=ev[6];  s.w=ev[7];  *reinterpret_cast<float4*>(bp+4)  = s;
        s.x=ev[8];  s.y=ev[9];  s.z=ev[10]; s.w=ev[11]; *reinterpret_cast<float4*>(bp+8)  = s;
        s.x=ev[12]; s.y=ev[13]; s.z=ev[14]; s.w=ev[15]; *reinterpret_cast<float4*>(bp+12) = s;
        s.x=ev[16]; s.y=ev[17]; s.z=ev[18]; s.w=ev[19]; *reinterpret_cast<float4*>(bp+16) = s;
        s.x=ev[20]; s.y=ev[21]; s.z=ev[22]; s.w=ev[23]; *reinterpret_cast<float4*>(bp+20) = s;
        s.x=ev[24]; s.y=ev[25]; s.z=ev[26]; s.w=ev[27]; *reinterpret_cast<float4*>(bp+24) = s;
        s.x=ev[28]; s.y=ev[29]; s.z=ev[30]; s.w=ev[31]; *reinterpret_cast<float4*>(bp+28) = s;
    }
    __syncthreads();

    // ---- coalesced float4 writeout ----
    float4* o4 = (float4*)(outr + (t0 - PADLEN));
    #pragma unroll
    for (int k = 0; k < S_OUT / 4 / T_THREADS; ++k) {     // 8 iters
        int e = tid + k * T_THREADS;
        float4 v = *reinterpret_cast<const float4*>(&buf[PH(4 * e)]);
        o4[e] = v;
    }
}

extern "C" void kernel_launch(void* const* d_in, const int* in_sizes, int n_in,
                              void* d_out, int out_size)
{
    const float* x = (const float*)d_in[0];
    float* out = (float*)d_out;

    const int rows = in_sizes[0] / N_SAMP;  // 1024
    dim3 grid(N_CHUNKS, rows);
    filtfilt_kernel<<<grid, T_THREADS>>>(x, out);
}